// round 1
// baseline (speedup 1.0000x reference)
#include <cuda_runtime.h>
#include <cuda_bf16.h>

#define BS_   8
#define SEQ_  1024
#define DM_   1024
#define H_    16
#define DK_   64
#define BH_   (BS_ * H_)     // 128
#define M_    (BS_ * SEQ_)   // 8192

// Scratch (allocation-free rule: __device__ globals)
__device__ float g_Q[BH_ * SEQ_ * DK_];   // [b,h,s,d] 32MB
__device__ float g_K[BH_ * SEQ_ * DK_];
__device__ float g_V[BH_ * SEQ_ * DK_];
__device__ float g_ctx[M_ * DM_];         // [b*s, h*dk] 32MB

// ---------------------------------------------------------------------------
// Tiled fp32 GEMM:  C[M,N] = A[M,K] @ B[K,N] + bias[N]
// headLayout=1: scatter C[m,n] to [((b*H+h)*S+s)*DK+d] with b=m/S,s=m%S,h=n/DK,d=n%DK
// BM=BN=128, BK=8, 256 threads, 8x8 microtile per thread.
// ---------------------------------------------------------------------------
#define BM 128
#define BN 128
#define BKD 8

__global__ __launch_bounds__(256) void gemm_bias_kernel(
    const float* __restrict__ A, const float* __restrict__ B,
    const float* __restrict__ bias, float* __restrict__ C,
    int M, int N, int K, int headLayout)
{
    __shared__ float As[BKD][BM];
    __shared__ float Bs[BKD][BN];

    const int tid = threadIdx.x;
    const int bx = blockIdx.x;   // N tile
    const int by = blockIdx.y;   // M tile

    // A tile loads: 128 rows x 8 cols = 256 float4 (one per thread)
    const int aRow  = tid >> 1;
    const int aCol4 = (tid & 1) * 4;
    // B tile loads: 8 rows x 128 cols = 256 float4
    const int bRow  = tid >> 5;
    const int bCol4 = (tid & 31) * 4;

    const float* Aptr = A + (size_t)(by * BM + aRow) * K + aCol4;
    const float* Bptr = B + (size_t)bRow * N + bx * BN + bCol4;

    const int tx = tid & 15;     // 16 col-threads
    const int ty = tid >> 4;     // 16 row-threads

    float acc[8][8];
#pragma unroll
    for (int i = 0; i < 8; i++)
#pragma unroll
        for (int j = 0; j < 8; j++) acc[i][j] = 0.f;

    for (int k0 = 0; k0 < K; k0 += BKD) {
        float4 av = *(const float4*)(Aptr + k0);
        float4 bv = *(const float4*)(Bptr + (size_t)k0 * N);
        __syncthreads();
        As[aCol4 + 0][aRow] = av.x;
        As[aCol4 + 1][aRow] = av.y;
        As[aCol4 + 2][aRow] = av.z;
        As[aCol4 + 3][aRow] = av.w;
        *(float4*)&Bs[bRow][bCol4] = bv;
        __syncthreads();

#pragma unroll
        for (int kk = 0; kk < BKD; kk++) {
            float4 a0 = *(const float4*)&As[kk][ty * 4];
            float4 a1 = *(const float4*)&As[kk][64 + ty * 4];
            float4 b0 = *(const float4*)&Bs[kk][tx * 4];
            float4 b1 = *(const float4*)&Bs[kk][64 + tx * 4];
            float ra[8] = {a0.x, a0.y, a0.z, a0.w, a1.x, a1.y, a1.z, a1.w};
            float rb[8] = {b0.x, b0.y, b0.z, b0.w, b1.x, b1.y, b1.z, b1.w};
#pragma unroll
            for (int i = 0; i < 8; i++)
#pragma unroll
                for (int j = 0; j < 8; j++)
                    acc[i][j] = fmaf(ra[i], rb[j], acc[i][j]);
        }
    }

#pragma unroll
    for (int ri = 0; ri < 8; ri++) {
        int m = by * BM + ((ri < 4) ? (ty * 4 + ri) : (64 + ty * 4 + ri - 4));
#pragma unroll
        for (int ci = 0; ci < 8; ci++) {
            int n = bx * BN + ((ci < 4) ? (tx * 4 + ci) : (64 + tx * 4 + ci - 4));
            float val = acc[ri][ci] + bias[n];
            if (headLayout) {
                int b = m >> 10;          // m / SEQ
                int s = m & 1023;
                int h = n >> 6;           // n / DK
                int d = n & 63;
                C[(((size_t)(b * H_ + h) * SEQ_) + s) * DK_ + d] = val;
            } else {
                C[(size_t)m * N + n] = val;
            }
        }
    }
}

// ---------------------------------------------------------------------------
// Flash-style attention. One block = 128 query rows for one (b,h).
// One thread = one query row: q[64] + ctx acc[64] in registers, online softmax.
// Key/Value tiles of 16 staged in smem (broadcast reads).
// ---------------------------------------------------------------------------
#define KT 16

__global__ __launch_bounds__(128) void attention_kernel(
    const float* __restrict__ Q, const float* __restrict__ Kh,
    const float* __restrict__ Vh, const int* __restrict__ mask,
    float* __restrict__ ctx)
{
    __shared__ float Ks[KT][DK_];
    __shared__ float Vs[KT][DK_];

    const int bh = blockIdx.x;          // 0..127
    const int b  = bh >> 4;
    const int h  = bh & 15;
    const int q  = blockIdx.y * 128 + threadIdx.x;

    const float* qp = Q + ((size_t)bh * SEQ_ + q) * DK_;
    float qreg[DK_];
#pragma unroll
    for (int d = 0; d < DK_; d += 4) {
        float4 v = *(const float4*)(qp + d);
        qreg[d] = v.x; qreg[d+1] = v.y; qreg[d+2] = v.z; qreg[d+3] = v.w;
    }

    float acc[DK_];
#pragma unroll
    for (int d = 0; d < DK_; d++) acc[d] = 0.f;
    float mrun = -3.0e38f;
    float lrun = 0.f;
    const float scale = 0.125f;   // 1/sqrt(64)

    const int*   mrow  = mask + ((size_t)b * SEQ_ + q) * SEQ_;
    const float* Kbase = Kh + (size_t)bh * SEQ_ * DK_;
    const float* Vbase = Vh + (size_t)bh * SEQ_ * DK_;

    for (int k0 = 0; k0 < SEQ_; k0 += KT) {
        __syncthreads();
        // load KT x 64 floats for K and V: KT*16 float4 each
#pragma unroll
        for (int i = threadIdx.x; i < KT * (DK_ / 4); i += 128) {
            int r = i >> 4;
            int c = (i & 15) * 4;
            *(float4*)&Ks[r][c] = *(const float4*)(Kbase + (size_t)(k0 + r) * DK_ + c);
            *(float4*)&Vs[r][c] = *(const float4*)(Vbase + (size_t)(k0 + r) * DK_ + c);
        }
        __syncthreads();

        float sv[KT];
#pragma unroll
        for (int j = 0; j < KT; j++) {
            float s0 = 0.f, s1 = 0.f, s2 = 0.f, s3 = 0.f;
#pragma unroll
            for (int d = 0; d < DK_; d += 4) {
                float4 kv = *(const float4*)&Ks[j][d];
                s0 = fmaf(qreg[d],     kv.x, s0);
                s1 = fmaf(qreg[d + 1], kv.y, s1);
                s2 = fmaf(qreg[d + 2], kv.z, s2);
                s3 = fmaf(qreg[d + 3], kv.w, s3);
            }
            sv[j] = (s0 + s1) + (s2 + s3);
        }

        float mt = mrun;
#pragma unroll
        for (int j = 0; j < KT; j++) {
            sv[j] = (mrow[k0 + j] != 0) ? sv[j] * scale : -1e9f;
            mt = fmaxf(mt, sv[j]);
        }

        float alpha = __expf(mrun - mt);
        lrun *= alpha;
#pragma unroll
        for (int d = 0; d < DK_; d++) acc[d] *= alpha;

#pragma unroll
        for (int j = 0; j < KT; j++) {
            float p = __expf(sv[j] - mt);
            lrun += p;
#pragma unroll
            for (int d = 0; d < DK_; d += 4) {
                float4 vv = *(const float4*)&Vs[j][d];
                acc[d]     = fmaf(p, vv.x, acc[d]);
                acc[d + 1] = fmaf(p, vv.y, acc[d + 1]);
                acc[d + 2] = fmaf(p, vv.z, acc[d + 2]);
                acc[d + 3] = fmaf(p, vv.w, acc[d + 3]);
            }
        }
        mrun = mt;
    }

    float inv = 1.f / lrun;
    float* op = ctx + ((size_t)(b * SEQ_ + q)) * DM_ + h * DK_;
#pragma unroll
    for (int d = 0; d < DK_; d += 4) {
        float4 v;
        v.x = acc[d] * inv; v.y = acc[d+1] * inv;
        v.z = acc[d+2] * inv; v.w = acc[d+3] * inv;
        *(float4*)(op + d) = v;
    }
}

// ---------------------------------------------------------------------------
extern "C" void kernel_launch(void* const* d_in, const int* in_sizes, int n_in,
                              void* d_out, int out_size)
{
    const float* q    = (const float*)d_in[0];
    const float* k    = (const float*)d_in[1];
    const float* v    = (const float*)d_in[2];
    const int*   mask = (const int*)  d_in[3];
    const float* Wq   = (const float*)d_in[4];
    const float* bq   = (const float*)d_in[5];
    const float* Wk   = (const float*)d_in[6];
    const float* bk   = (const float*)d_in[7];
    const float* Wv   = (const float*)d_in[8];
    const float* bv   = (const float*)d_in[9];
    const float* Wo   = (const float*)d_in[10];
    const float* bo   = (const float*)d_in[11];
    float* out = (float*)d_out;

    float *pQ, *pK, *pV, *pCtx;
    cudaGetSymbolAddress((void**)&pQ,   g_Q);
    cudaGetSymbolAddress((void**)&pK,   g_K);
    cudaGetSymbolAddress((void**)&pV,   g_V);
    cudaGetSymbolAddress((void**)&pCtx, g_ctx);

    dim3 gemmGrid(DM_ / BN, M_ / BM);   // (8, 64)
    gemm_bias_kernel<<<gemmGrid, 256>>>(q, Wq, bq, pQ, M_, DM_, DM_, 1);
    gemm_bias_kernel<<<gemmGrid, 256>>>(k, Wk, bk, pK, M_, DM_, DM_, 1);
    gemm_bias_kernel<<<gemmGrid, 256>>>(v, Wv, bv, pV, M_, DM_, DM_, 1);

    dim3 attnGrid(BH_, SEQ_ / 128);     // (128, 8)
    attention_kernel<<<attnGrid, 128>>>(pQ, pK, pV, mask, pCtx);

    gemm_bias_kernel<<<gemmGrid, 256>>>(pCtx, Wo, bo, out, M_, DM_, DM_, 0);
}

// round 3
// speedup vs baseline: 1.3564x; 1.3564x over previous
#include <cuda.h>
#include <cuda_runtime.h>
#include <cuda_bf16.h>
#include <cstdint>

#define BS_   8
#define SEQ_  1024
#define DM_   1024
#define H_    16
#define DK_   64
#define BH_   (BS_ * H_)     // 128
#define M_    (BS_ * SEQ_)   // 8192

// ---------------- scratch (__device__ globals; no allocs allowed) ----------
__device__ float g_Q[BH_ * SEQ_ * DK_];           // [b,h,s,d]
__device__ float g_K[BH_ * SEQ_ * DK_];
__device__ float g_V[BH_ * SEQ_ * DK_];
__device__ float g_ctx[M_ * DM_];                 // [b*s, h*dk]
__device__ __nv_bfloat16 g_ahi[M_ * DM_];         // activation split
__device__ __nv_bfloat16 g_alo[M_ * DM_];
__device__ __nv_bfloat16 g_whi[DM_ * DM_];        // weight split, TRANSPOSED [N,K]
__device__ __nv_bfloat16 g_wlo[DM_ * DM_];

// ---------------- helpers ---------------------------------------------------
__device__ __forceinline__ uint32_t smem_u32(const void* p) {
    uint32_t a;
    asm("{ .reg .u64 t; cvta.to.shared.u64 t, %1; cvt.u32.u64 %0, t; }" : "=r"(a) : "l"(p));
    return a;
}
#define SW128(off) ((off) ^ (((off) >> 3) & 0x70))

#define CP_ASYNC16(saddr, gaddr) \
    asm volatile("cp.async.cg.shared.global [%0], [%1], 16;" :: "r"(saddr), "l"(gaddr))
#define CP_COMMIT() asm volatile("cp.async.commit_group;" ::: "memory")
#define CP_WAIT(n)  asm volatile("cp.async.wait_group %0;" :: "n"(n) : "memory")

#define LDMX4(r, addr) \
    asm volatile("ldmatrix.sync.aligned.m8n8.x4.shared.b16 {%0,%1,%2,%3}, [%4];" \
        : "=r"((r)[0]), "=r"((r)[1]), "=r"((r)[2]), "=r"((r)[3]) : "r"(addr))

#define MMA16816(c, a, b0, b1) \
    asm volatile("mma.sync.aligned.m16n8k16.row.col.f32.bf16.bf16.f32 " \
        "{%0,%1,%2,%3}, {%4,%5,%6,%7}, {%8,%9}, {%0,%1,%2,%3};" \
        : "+f"((c)[0]), "+f"((c)[1]), "+f"((c)[2]), "+f"((c)[3]) \
        : "r"((a)[0]), "r"((a)[1]), "r"((a)[2]), "r"((a)[3]), "r"(b0), "r"(b1))

// ---------------- split conversion kernels ---------------------------------
__global__ __launch_bounds__(256) void split_kernel(
    const float* __restrict__ X, __nv_bfloat16* __restrict__ hi,
    __nv_bfloat16* __restrict__ lo, int n)
{
    int i = (blockIdx.x * 256 + threadIdx.x) * 4;
    if (i >= n) return;
    float4 v = *(const float4*)(X + i);
    float f[4] = {v.x, v.y, v.z, v.w};
    __nv_bfloat16 h[4], l[4];
#pragma unroll
    for (int j = 0; j < 4; j++) {
        h[j] = __float2bfloat16_rn(f[j]);
        l[j] = __float2bfloat16_rn(f[j] - __bfloat162float(h[j]));
    }
    *(uint2*)(hi + i) = *(uint2*)h;
    *(uint2*)(lo + i) = *(uint2*)l;
}

// W[K,N] fp32 -> hiT/loT [N,K] bf16 (transposed)
__global__ __launch_bounds__(256) void wsplit_kernel(
    const float* __restrict__ W, __nv_bfloat16* __restrict__ hiT,
    __nv_bfloat16* __restrict__ loT)
{
    __shared__ float tile[32][33];
    int x = blockIdx.x * 32 + threadIdx.x;
    int y = blockIdx.y * 32 + threadIdx.y;
#pragma unroll
    for (int j = 0; j < 32; j += 8)
        tile[threadIdx.y + j][threadIdx.x] = W[(size_t)(y + j) * DM_ + x];
    __syncthreads();
    int x2 = blockIdx.y * 32 + threadIdx.x;
    int y2 = blockIdx.x * 32 + threadIdx.y;
#pragma unroll
    for (int j = 0; j < 32; j += 8) {
        float f = tile[threadIdx.x][threadIdx.y + j];
        __nv_bfloat16 h = __float2bfloat16_rn(f);
        __nv_bfloat16 l = __float2bfloat16_rn(f - __bfloat162float(h));
        hiT[(size_t)(y2 + j) * DM_ + x2] = h;
        loT[(size_t)(y2 + j) * DM_ + x2] = l;
    }
}

// ---------------- mma.sync bf16-split GEMM ----------------------------------
// C[M,N] = (Ahi+Alo)[M,K] @ (BThi+BTlo)^T + bias. Tiles: 128x128, BK=64.
// Double-buffered smem via cp.async. 8 warps, each 64x32 via m16n8k16.
#define NKCH  16          // 1024 / 64
#define STAGE_BYTES 65536 // 4 tiles x 16KB
#define GEMM_SMEM  (2 * STAGE_BYTES)

__device__ __forceinline__ void issue_chunk(
    uint32_t sstage, const __nv_bfloat16* pAhi, const __nv_bfloat16* pAlo,
    const __nv_bfloat16* pBhi, const __nv_bfloat16* pBlo, int kc, int tid)
{
    const __nv_bfloat16* srcs[4] = {pAhi + kc, pAlo + kc, pBhi + kc, pBlo + kc};
#pragma unroll
    for (int t = 0; t < 4; t++) {
        uint32_t sb = sstage + t * 16384;
#pragma unroll
        for (int i = 0; i < 4; i++) {
            int idx = i * 256 + tid;
            int row = idx >> 3;
            int c   = idx & 7;
            const void* g = srcs[t] + (size_t)row * DM_ + c * 8;
            uint32_t s = sb + SW128(row * 128 + c * 16);
            CP_ASYNC16(s, g);
        }
    }
}

__global__ __launch_bounds__(256, 1) void gemm_mma_kernel(
    const __nv_bfloat16* __restrict__ Ahi, const __nv_bfloat16* __restrict__ Alo,
    const __nv_bfloat16* __restrict__ BThi, const __nv_bfloat16* __restrict__ BTlo,
    const float* __restrict__ bias, float* __restrict__ C, int headLayout)
{
    extern __shared__ char smem[];
    const uint32_t sbase = smem_u32(smem);
    const int tid   = threadIdx.x;
    const int wid   = tid >> 5;
    const int lane  = tid & 31;
    const int warpM = wid >> 2;       // 0..1
    const int warpN = wid & 3;        // 0..3
    const int tile_m = blockIdx.y * 128;
    const int tile_n = blockIdx.x * 128;

    const __nv_bfloat16* pAhi = Ahi  + (size_t)tile_m * DM_;
    const __nv_bfloat16* pAlo = Alo  + (size_t)tile_m * DM_;
    const __nv_bfloat16* pBhi = BThi + (size_t)tile_n * DM_;
    const __nv_bfloat16* pBlo = BTlo + (size_t)tile_n * DM_;

    float acc[4][4][4];
#pragma unroll
    for (int i = 0; i < 4; i++)
#pragma unroll
        for (int j = 0; j < 4; j++)
#pragma unroll
            for (int r = 0; r < 4; r++) acc[i][j][r] = 0.f;

    issue_chunk(sbase, pAhi, pAlo, pBhi, pBlo, 0, tid);
    CP_COMMIT();

    const int aRow = lane & 15;
    const int aCol = lane >> 4;       // 0..1

    for (int ic = 0; ic < NKCH; ic++) {
        if (ic + 1 < NKCH) {
            issue_chunk(sbase + ((ic + 1) & 1) * STAGE_BYTES,
                        pAhi, pAlo, pBhi, pBlo, (ic + 1) * 64, tid);
            CP_COMMIT();
            CP_WAIT(1);
        } else {
            CP_WAIT(0);
        }
        __syncthreads();

        const uint32_t ss = sbase + (ic & 1) * STAGE_BYTES;
#pragma unroll
        for (int ks = 0; ks < 4; ks++) {
            const int kb = ks * 32 + aCol * 16;   // byte offset within 128B row
            uint32_t ah[4][4], al[4][4];
#pragma unroll
            for (int mt = 0; mt < 4; mt++) {
                uint32_t ad = ss + SW128((warpM * 64 + mt * 16 + aRow) * 128 + kb);
                LDMX4(ah[mt], ad);
                LDMX4(al[mt], ad + 16384);
            }
            uint32_t bh[2][4], bl[2][4];
#pragma unroll
            for (int p = 0; p < 2; p++) {
                uint32_t bd = ss + 32768 + SW128((warpN * 32 + p * 16 + aRow) * 128 + kb);
                LDMX4(bh[p], bd);
                LDMX4(bl[p], bd + 16384);
            }
#pragma unroll
            for (int mt = 0; mt < 4; mt++) {
#pragma unroll
                for (int nt = 0; nt < 4; nt++) {
                    const int p = nt >> 1, q = nt & 1;
                    MMA16816(acc[mt][nt], ah[mt], bh[p][q], bh[p][q + 2]);
                    MMA16816(acc[mt][nt], ah[mt], bl[p][q], bl[p][q + 2]);
                    MMA16816(acc[mt][nt], al[mt], bh[p][q], bh[p][q + 2]);
                }
            }
        }
        __syncthreads();
    }

    // epilogue
    const int group = lane >> 2;
    const int tid4  = lane & 3;
#pragma unroll
    for (int mt = 0; mt < 4; mt++) {
#pragma unroll
        for (int nt = 0; nt < 4; nt++) {
            const int n  = tile_n + warpN * 32 + nt * 8 + tid4 * 2;
            const float bx = bias[n], by = bias[n + 1];
#pragma unroll
            for (int rr = 0; rr < 2; rr++) {
                const int m = tile_m + warpM * 64 + mt * 16 + group + rr * 8;
                float2 v;
                v.x = acc[mt][nt][rr * 2]     + bx;
                v.y = acc[mt][nt][rr * 2 + 1] + by;
                if (headLayout) {
                    const int b = m >> 10, s = m & 1023;
                    const int h = n >> 6,  d = n & 63;
                    *(float2*)(C + (((size_t)(b * H_ + h) * SEQ_) + s) * DK_ + d) = v;
                } else {
                    *(float2*)(C + (size_t)m * DM_ + n) = v;
                }
            }
        }
    }
}

// ---------------- flash attention (unchanged, fp32) -------------------------
#define KT 16
__global__ __launch_bounds__(128) void attention_kernel(
    const float* __restrict__ Q, const float* __restrict__ Kh,
    const float* __restrict__ Vh, const int* __restrict__ mask,
    float* __restrict__ ctx)
{
    __shared__ float Ks[KT][DK_];
    __shared__ float Vs[KT][DK_];

    const int bh = blockIdx.x;
    const int b  = bh >> 4;
    const int h  = bh & 15;
    const int q  = blockIdx.y * 128 + threadIdx.x;

    const float* qp = Q + ((size_t)bh * SEQ_ + q) * DK_;
    float qreg[DK_];
#pragma unroll
    for (int d = 0; d < DK_; d += 4) {
        float4 v = *(const float4*)(qp + d);
        qreg[d] = v.x; qreg[d+1] = v.y; qreg[d+2] = v.z; qreg[d+3] = v.w;
    }
    float acc[DK_];
#pragma unroll
    for (int d = 0; d < DK_; d++) acc[d] = 0.f;
    float mrun = -3.0e38f, lrun = 0.f;
    const float scale = 0.125f;

    const int*   mrow  = mask + ((size_t)b * SEQ_ + q) * SEQ_;
    const float* Kbase = Kh + (size_t)bh * SEQ_ * DK_;
    const float* Vbase = Vh + (size_t)bh * SEQ_ * DK_;

    for (int k0 = 0; k0 < SEQ_; k0 += KT) {
        __syncthreads();
#pragma unroll
        for (int i = threadIdx.x; i < KT * (DK_ / 4); i += 128) {
            int r = i >> 4, c = (i & 15) * 4;
            *(float4*)&Ks[r][c] = *(const float4*)(Kbase + (size_t)(k0 + r) * DK_ + c);
            *(float4*)&Vs[r][c] = *(const float4*)(Vbase + (size_t)(k0 + r) * DK_ + c);
        }
        __syncthreads();

        float sv[KT];
#pragma unroll
        for (int j = 0; j < KT; j++) {
            float s0 = 0.f, s1 = 0.f, s2 = 0.f, s3 = 0.f;
#pragma unroll
            for (int d = 0; d < DK_; d += 4) {
                float4 kv = *(const float4*)&Ks[j][d];
                s0 = fmaf(qreg[d],     kv.x, s0);
                s1 = fmaf(qreg[d + 1], kv.y, s1);
                s2 = fmaf(qreg[d + 2], kv.z, s2);
                s3 = fmaf(qreg[d + 3], kv.w, s3);
            }
            sv[j] = (s0 + s1) + (s2 + s3);
        }
        float mt = mrun;
#pragma unroll
        for (int j = 0; j < KT; j++) {
            sv[j] = (mrow[k0 + j] != 0) ? sv[j] * scale : -1e9f;
            mt = fmaxf(mt, sv[j]);
        }
        float alpha = __expf(mrun - mt);
        lrun *= alpha;
#pragma unroll
        for (int d = 0; d < DK_; d++) acc[d] *= alpha;
#pragma unroll
        for (int j = 0; j < KT; j++) {
            float p = __expf(sv[j] - mt);
            lrun += p;
#pragma unroll
            for (int d = 0; d < DK_; d += 4) {
                float4 vv = *(const float4*)&Vs[j][d];
                acc[d]     = fmaf(p, vv.x, acc[d]);
                acc[d + 1] = fmaf(p, vv.y, acc[d + 1]);
                acc[d + 2] = fmaf(p, vv.z, acc[d + 2]);
                acc[d + 3] = fmaf(p, vv.w, acc[d + 3]);
            }
        }
        mrun = mt;
    }
    float inv = 1.f / lrun;
    float* op = ctx + ((size_t)(b * SEQ_ + q)) * DM_ + h * DK_;
#pragma unroll
    for (int d = 0; d < DK_; d += 4) {
        float4 v;
        v.x = acc[d] * inv; v.y = acc[d+1] * inv;
        v.z = acc[d+2] * inv; v.w = acc[d+3] * inv;
        *(float4*)(op + d) = v;
    }
}

// ---------------------------------------------------------------------------
extern "C" void kernel_launch(void* const* d_in, const int* in_sizes, int n_in,
                              void* d_out, int out_size)
{
    const float* q    = (const float*)d_in[0];
    const float* k    = (const float*)d_in[1];
    const float* v    = (const float*)d_in[2];
    const int*   mask = (const int*)  d_in[3];
    const float* Wq   = (const float*)d_in[4];
    const float* bq   = (const float*)d_in[5];
    const float* Wk   = (const float*)d_in[6];
    const float* bk   = (const float*)d_in[7];
    const float* Wv   = (const float*)d_in[8];
    const float* bv   = (const float*)d_in[9];
    const float* Wo   = (const float*)d_in[10];
    const float* bo   = (const float*)d_in[11];
    float* out = (float*)d_out;

    float *pQ, *pK, *pV, *pCtx;
    __nv_bfloat16 *pAhi, *pAlo, *pWhi, *pWlo;
    cudaGetSymbolAddress((void**)&pQ,   g_Q);
    cudaGetSymbolAddress((void**)&pK,   g_K);
    cudaGetSymbolAddress((void**)&pV,   g_V);
    cudaGetSymbolAddress((void**)&pCtx, g_ctx);
    cudaGetSymbolAddress((void**)&pAhi, g_ahi);
    cudaGetSymbolAddress((void**)&pAlo, g_alo);
    cudaGetSymbolAddress((void**)&pWhi, g_whi);
    cudaGetSymbolAddress((void**)&pWlo, g_wlo);

    cudaFuncSetAttribute(gemm_mma_kernel, cudaFuncAttributeMaxDynamicSharedMemorySize, GEMM_SMEM);

    const int nElem = M_ * DM_;
    dim3 splitGrid(nElem / 4 / 256);
    dim3 wGrid(32, 32), wBlock(32, 8);
    dim3 gemmGrid(DM_ / 128, M_ / 128);   // (8, 64)

    wsplit_kernel<<<wGrid, wBlock>>>(Wq, pWhi, pWlo);
    split_kernel<<<splitGrid, 256>>>(q, pAhi, pAlo, nElem);
    gemm_mma_kernel<<<gemmGrid, 256, GEMM_SMEM>>>(pAhi, pAlo, pWhi, pWlo, bq, pQ, 1);

    wsplit_kernel<<<wGrid, wBlock>>>(Wk, pWhi, pWlo);
    split_kernel<<<splitGrid, 256>>>(k, pAhi, pAlo, nElem);
    gemm_mma_kernel<<<gemmGrid, 256, GEMM_SMEM>>>(pAhi, pAlo, pWhi, pWlo, bk, pK, 1);

    wsplit_kernel<<<wGrid, wBlock>>>(Wv, pWhi, pWlo);
    split_kernel<<<splitGrid, 256>>>(v, pAhi, pAlo, nElem);
    gemm_mma_kernel<<<gemmGrid, 256, GEMM_SMEM>>>(pAhi, pAlo, pWhi, pWlo, bv, pV, 1);

    dim3 attnGrid(BH_, SEQ_ / 128);
    attention_kernel<<<attnGrid, 128>>>(pQ, pK, pV, mask, pCtx);

    wsplit_kernel<<<wGrid, wBlock>>>(Wo, pWhi, pWlo);
    split_kernel<<<splitGrid, 256>>>(pCtx, pAhi, pAlo, nElem);
    gemm_mma_kernel<<<gemmGrid, 256, GEMM_SMEM>>>(pAhi, pAlo, pWhi, pWlo, bo, out, 0);
}

// round 4
// speedup vs baseline: 2.9645x; 2.1855x over previous
#include <cuda.h>
#include <cuda_runtime.h>
#include <cuda_bf16.h>
#include <cstdint>

#define BS_   8
#define SEQ_  1024
#define DM_   1024
#define H_    16
#define DK_   64
#define BH_   (BS_ * H_)     // 128
#define M_    (BS_ * SEQ_)   // 8192

// ---------------- scratch (__device__ globals; no allocs allowed) ----------
__device__ __nv_bfloat16 g_qhi[BH_ * SEQ_ * DK_];   // [b,h,s,d]
__device__ __nv_bfloat16 g_qlo[BH_ * SEQ_ * DK_];
__device__ __nv_bfloat16 g_khi[BH_ * SEQ_ * DK_];
__device__ __nv_bfloat16 g_klo[BH_ * SEQ_ * DK_];
__device__ __nv_bfloat16 g_vhi[BH_ * SEQ_ * DK_];
__device__ __nv_bfloat16 g_vlo[BH_ * SEQ_ * DK_];
__device__ __nv_bfloat16 g_ahi[M_ * DM_];           // activations / ctx split
__device__ __nv_bfloat16 g_alo[M_ * DM_];
__device__ __nv_bfloat16 g_whi[DM_ * DM_];          // weight split, TRANSPOSED [N,K]
__device__ __nv_bfloat16 g_wlo[DM_ * DM_];

// ---------------- helpers ---------------------------------------------------
__device__ __forceinline__ uint32_t smem_u32(const void* p) {
    uint32_t a;
    asm("{ .reg .u64 t; cvta.to.shared.u64 t, %1; cvt.u32.u64 %0, t; }" : "=r"(a) : "l"(p));
    return a;
}
#define SW128(off) ((off) ^ (((off) >> 3) & 0x70))

#define CP_ASYNC16(saddr, gaddr) \
    asm volatile("cp.async.cg.shared.global [%0], [%1], 16;" :: "r"(saddr), "l"(gaddr))
#define CP_COMMIT() asm volatile("cp.async.commit_group;" ::: "memory")
#define CP_WAIT(n)  asm volatile("cp.async.wait_group %0;" :: "n"(n) : "memory")

#define LDMX4(r, addr) \
    asm volatile("ldmatrix.sync.aligned.m8n8.x4.shared.b16 {%0,%1,%2,%3}, [%4];" \
        : "=r"((r)[0]), "=r"((r)[1]), "=r"((r)[2]), "=r"((r)[3]) : "r"(addr))
#define LDMX4T(r, addr) \
    asm volatile("ldmatrix.sync.aligned.m8n8.x4.trans.shared.b16 {%0,%1,%2,%3}, [%4];" \
        : "=r"((r)[0]), "=r"((r)[1]), "=r"((r)[2]), "=r"((r)[3]) : "r"(addr))

#define MMA16816(c, a, b0, b1) \
    asm volatile("mma.sync.aligned.m16n8k16.row.col.f32.bf16.bf16.f32 " \
        "{%0,%1,%2,%3}, {%4,%5,%6,%7}, {%8,%9}, {%0,%1,%2,%3};" \
        : "+f"((c)[0]), "+f"((c)[1]), "+f"((c)[2]), "+f"((c)[3]) \
        : "r"((a)[0]), "r"((a)[1]), "r"((a)[2]), "r"((a)[3]), "r"(b0), "r"(b1))

__device__ __forceinline__ uint16_t bf_hi(float v) {
    return __bfloat16_as_ushort(__float2bfloat16_rn(v));
}
__device__ __forceinline__ float bf_res(float v, uint16_t h) {
    return v - __bfloat162float(__ushort_as_bfloat16(h));
}
__device__ __forceinline__ uint32_t pk(uint16_t lo, uint16_t hi) {
    return ((uint32_t)hi << 16) | lo;
}

// ---------------- split conversion kernels ---------------------------------
__global__ __launch_bounds__(256) void split_kernel(
    const float* __restrict__ X, __nv_bfloat16* __restrict__ hi,
    __nv_bfloat16* __restrict__ lo, int n)
{
    int i = (blockIdx.x * 256 + threadIdx.x) * 4;
    if (i >= n) return;
    float4 v = *(const float4*)(X + i);
    float f[4] = {v.x, v.y, v.z, v.w};
    __nv_bfloat16 h[4], l[4];
#pragma unroll
    for (int j = 0; j < 4; j++) {
        h[j] = __float2bfloat16_rn(f[j]);
        l[j] = __float2bfloat16_rn(f[j] - __bfloat162float(h[j]));
    }
    *(uint2*)(hi + i) = *(uint2*)h;
    *(uint2*)(lo + i) = *(uint2*)l;
}

// W[K,N] fp32 -> hiT/loT [N,K] bf16 (transposed)
__global__ __launch_bounds__(256) void wsplit_kernel(
    const float* __restrict__ W, __nv_bfloat16* __restrict__ hiT,
    __nv_bfloat16* __restrict__ loT)
{
    __shared__ float tile[32][33];
    int x = blockIdx.x * 32 + threadIdx.x;
    int y = blockIdx.y * 32 + threadIdx.y;
#pragma unroll
    for (int j = 0; j < 32; j += 8)
        tile[threadIdx.y + j][threadIdx.x] = W[(size_t)(y + j) * DM_ + x];
    __syncthreads();
    int x2 = blockIdx.y * 32 + threadIdx.x;
    int y2 = blockIdx.x * 32 + threadIdx.y;
#pragma unroll
    for (int j = 0; j < 32; j += 8) {
        float f = tile[threadIdx.x][threadIdx.y + j];
        __nv_bfloat16 h = __float2bfloat16_rn(f);
        __nv_bfloat16 l = __float2bfloat16_rn(f - __bfloat162float(h));
        hiT[(size_t)(y2 + j) * DM_ + x2] = h;
        loT[(size_t)(y2 + j) * DM_ + x2] = l;
    }
}

// ---------------- mma.sync bf16-split GEMM ----------------------------------
// C = (Ahi+Alo)[M,K] @ (BThi+BTlo)^T + bias. 128x128 tiles, BK=64, cp.async x2.
// mode 0: fp32 C row-major.  mode 1: bf16 hi/lo split, head layout [bh,s,d].
#define NKCH  16
#define STAGE_BYTES 65536
#define GEMM_SMEM  (2 * STAGE_BYTES)

__device__ __forceinline__ void issue_chunk(
    uint32_t sstage, const __nv_bfloat16* pAhi, const __nv_bfloat16* pAlo,
    const __nv_bfloat16* pBhi, const __nv_bfloat16* pBlo, int kc, int tid)
{
    const __nv_bfloat16* srcs[4] = {pAhi + kc, pAlo + kc, pBhi + kc, pBlo + kc};
#pragma unroll
    for (int t = 0; t < 4; t++) {
        uint32_t sbuf = sstage + t * 16384;
#pragma unroll
        for (int i = 0; i < 4; i++) {
            int idx = i * 256 + tid;
            int row = idx >> 3;
            int c   = idx & 7;
            CP_ASYNC16(sbuf + SW128(row * 128 + c * 16), srcs[t] + (size_t)row * DM_ + c * 8);
        }
    }
}

__global__ __launch_bounds__(256, 1) void gemm_mma_kernel(
    const __nv_bfloat16* __restrict__ Ahi, const __nv_bfloat16* __restrict__ Alo,
    const __nv_bfloat16* __restrict__ BThi, const __nv_bfloat16* __restrict__ BTlo,
    const float* __restrict__ bias, float* __restrict__ C,
    __nv_bfloat16* __restrict__ outHi, __nv_bfloat16* __restrict__ outLo, int mode)
{
    extern __shared__ char smem[];
    const uint32_t sbase = smem_u32(smem);
    const int tid   = threadIdx.x;
    const int wid   = tid >> 5;
    const int lane  = tid & 31;
    const int warpM = wid >> 2;
    const int warpN = wid & 3;
    const int tile_m = blockIdx.y * 128;
    const int tile_n = blockIdx.x * 128;

    const __nv_bfloat16* pAhi = Ahi  + (size_t)tile_m * DM_;
    const __nv_bfloat16* pAlo = Alo  + (size_t)tile_m * DM_;
    const __nv_bfloat16* pBhi = BThi + (size_t)tile_n * DM_;
    const __nv_bfloat16* pBlo = BTlo + (size_t)tile_n * DM_;

    float acc[4][4][4];
#pragma unroll
    for (int i = 0; i < 4; i++)
#pragma unroll
        for (int j = 0; j < 4; j++)
#pragma unroll
            for (int r = 0; r < 4; r++) acc[i][j][r] = 0.f;

    issue_chunk(sbase, pAhi, pAlo, pBhi, pBlo, 0, tid);
    CP_COMMIT();

    const int aRow = lane & 15;
    const int aCol = lane >> 4;

    for (int ic = 0; ic < NKCH; ic++) {
        if (ic + 1 < NKCH) {
            issue_chunk(sbase + ((ic + 1) & 1) * STAGE_BYTES,
                        pAhi, pAlo, pBhi, pBlo, (ic + 1) * 64, tid);
            CP_COMMIT();
            CP_WAIT(1);
        } else {
            CP_WAIT(0);
        }
        __syncthreads();

        const uint32_t ss = sbase + (ic & 1) * STAGE_BYTES;
#pragma unroll
        for (int ks = 0; ks < 4; ks++) {
            const int kb = ks * 32 + aCol * 16;
            uint32_t ah[4][4], al[4][4];
#pragma unroll
            for (int mt = 0; mt < 4; mt++) {
                uint32_t ad = ss + SW128((warpM * 64 + mt * 16 + aRow) * 128 + kb);
                LDMX4(ah[mt], ad);
                LDMX4(al[mt], ad + 16384);
            }
            uint32_t bh[2][4], bl[2][4];
#pragma unroll
            for (int p = 0; p < 2; p++) {
                uint32_t bd = ss + 32768 + SW128((warpN * 32 + p * 16 + aRow) * 128 + kb);
                LDMX4(bh[p], bd);
                LDMX4(bl[p], bd + 16384);
            }
#pragma unroll
            for (int mt = 0; mt < 4; mt++) {
#pragma unroll
                for (int nt = 0; nt < 4; nt++) {
                    const int p = nt >> 1, q = nt & 1;
                    MMA16816(acc[mt][nt], ah[mt], bh[p][q], bh[p][q + 2]);
                    MMA16816(acc[mt][nt], ah[mt], bl[p][q], bl[p][q + 2]);
                    MMA16816(acc[mt][nt], al[mt], bh[p][q], bh[p][q + 2]);
                }
            }
        }
        __syncthreads();
    }

    const int group = lane >> 2;
    const int tid4  = lane & 3;
#pragma unroll
    for (int mt = 0; mt < 4; mt++) {
#pragma unroll
        for (int nt = 0; nt < 4; nt++) {
            const int n  = tile_n + warpN * 32 + nt * 8 + tid4 * 2;
            const float bx = bias[n], by = bias[n + 1];
#pragma unroll
            for (int rr = 0; rr < 2; rr++) {
                const int m = tile_m + warpM * 64 + mt * 16 + group + rr * 8;
                float vx = acc[mt][nt][rr * 2]     + bx;
                float vy = acc[mt][nt][rr * 2 + 1] + by;
                if (mode == 1) {
                    const int b = m >> 10, s = m & 1023;
                    const int h = n >> 6,  d = n & 63;
                    size_t off = (((size_t)(b * H_ + h) * SEQ_) + s) * DK_ + d;
                    uint16_t hx = bf_hi(vx), hy = bf_hi(vy);
                    *(uint32_t*)(outHi + off) = pk(hx, hy);
                    *(uint32_t*)(outLo + off) = pk(bf_hi(bf_res(vx, hx)), bf_hi(bf_res(vy, hy)));
                } else {
                    float2 v2; v2.x = vx; v2.y = vy;
                    *(float2*)(C + (size_t)m * DM_ + n) = v2;
                }
            }
        }
    }
}

// ---------------- tensor-core flash attention -------------------------------
// CTA: one (b,h), 128 q rows. 8 warps x 16 rows. Key tiles of 64, 2-stage.
// smem: QHI 0 (16K), QLO 16K, stages at 32K: [KHI, KLO, VHI, VLO] x 8K, x2.
#define AT_SMEM (32768 + 2 * 32768)

__device__ __forceinline__ void at_issue_stage(
    uint32_t sb, int buf, const __nv_bfloat16* kh, const __nv_bfloat16* kl,
    const __nv_bfloat16* vh, const __nv_bfloat16* vl, int tid)
{
    const __nv_bfloat16* srcs[4] = {kh, kl, vh, vl};
#pragma unroll
    for (int t = 0; t < 4; t++) {
        uint32_t dbase = sb + 32768 + buf * 32768 + t * 8192;
#pragma unroll
        for (int it = 0; it < 2; it++) {
            int idx = it * 256 + tid;
            int row = idx >> 3;
            int c   = idx & 7;
            CP_ASYNC16(dbase + SW128(row * 128 + c * 16), srcs[t] + row * DK_ + c * 8);
        }
    }
}

__global__ __launch_bounds__(256, 1) void attention_mma_kernel(
    const __nv_bfloat16* __restrict__ Qhi, const __nv_bfloat16* __restrict__ Qlo,
    const __nv_bfloat16* __restrict__ Khi, const __nv_bfloat16* __restrict__ Klo,
    const __nv_bfloat16* __restrict__ Vhi, const __nv_bfloat16* __restrict__ Vlo,
    const int* __restrict__ mask,
    __nv_bfloat16* __restrict__ Ohi, __nv_bfloat16* __restrict__ Olo)
{
    extern __shared__ char smem[];
    const uint32_t sb = smem_u32(smem);
    const int tid = threadIdx.x, wid = tid >> 5, lane = tid & 31;
    const int bh = blockIdx.x, b = bh >> 4, h = bh & 15, qt = blockIdx.y;
    const size_t headOff = (size_t)bh * SEQ_ * DK_;

    // Q tile (group 0)
    {
        const __nv_bfloat16* srcs[2] = {Qhi + headOff + (size_t)qt * 128 * DK_,
                                        Qlo + headOff + (size_t)qt * 128 * DK_};
#pragma unroll
        for (int t = 0; t < 2; t++)
#pragma unroll
            for (int it = 0; it < 4; it++) {
                int idx = it * 256 + tid;
                int row = idx >> 3, c = idx & 7;
                CP_ASYNC16(sb + t * 16384 + SW128(row * 128 + c * 16), srcs[t] + row * DK_ + c * 8);
            }
    }
    CP_COMMIT();
    at_issue_stage(sb, 0, Khi + headOff, Klo + headOff, Vhi + headOff, Vlo + headOff, tid);
    CP_COMMIT();
    CP_WAIT(1);
    __syncthreads();

    const int aRow = lane & 15;
    const int aCol = lane >> 4;
    const int g    = lane >> 2;
    const int c2   = (lane & 3) * 2;

    // Q fragments
    uint32_t qh[4][4], ql[4][4];
#pragma unroll
    for (int kc = 0; kc < 4; kc++) {
        uint32_t ad = sb + SW128((wid * 16 + aRow) * 128 + kc * 32 + aCol * 16);
        LDMX4(qh[kc], ad);
        LDMX4(ql[kc], ad + 16384);
    }

    float o[8][4];
#pragma unroll
    for (int j = 0; j < 8; j++)
#pragma unroll
        for (int r = 0; r < 4; r++) o[j][r] = 0.f;
    float m0 = -1e30f, m1 = -1e30f, l0 = 0.f, l1 = 0.f;
    const float scale = 0.125f;

    const int row0 = qt * 128 + wid * 16 + g;
    const int* mrow0 = mask + ((size_t)b * SEQ_ + row0) * SEQ_;
    const int* mrow1 = mrow0 + 8 * SEQ_;

    for (int kt = 0; kt < 16; kt++) {
        if (kt + 1 < 16) {
            size_t ko = headOff + (size_t)(kt + 1) * 64 * DK_;
            at_issue_stage(sb, (kt + 1) & 1, Khi + ko, Klo + ko, Vhi + ko, Vlo + ko, tid);
            CP_COMMIT();
            CP_WAIT(1);
        } else {
            CP_WAIT(0);
        }
        __syncthreads();
        const uint32_t ss = sb + 32768 + (kt & 1) * 32768;

        // ---- S = Qhi*Khi + Qhi*Klo + Qlo*Khi ----
        float c[8][4];
#pragma unroll
        for (int j = 0; j < 8; j++)
#pragma unroll
            for (int r = 0; r < 4; r++) c[j][r] = 0.f;
#pragma unroll
        for (int kc = 0; kc < 4; kc++) {
            const int kb = kc * 32 + aCol * 16;
#pragma unroll
            for (int jj = 0; jj < 4; jj++) {
                uint32_t kh_[4], kl_[4];
                uint32_t bd = ss + SW128((jj * 16 + aRow) * 128 + kb);
                LDMX4(kh_, bd);
                LDMX4(kl_, bd + 8192);
                MMA16816(c[2*jj],   qh[kc], kh_[0], kh_[2]);
                MMA16816(c[2*jj],   qh[kc], kl_[0], kl_[2]);
                MMA16816(c[2*jj],   ql[kc], kh_[0], kh_[2]);
                MMA16816(c[2*jj+1], qh[kc], kh_[1], kh_[3]);
                MMA16816(c[2*jj+1], qh[kc], kl_[1], kl_[3]);
                MMA16816(c[2*jj+1], ql[kc], kh_[1], kh_[3]);
            }
        }

        // ---- mask + scale ----
#pragma unroll
        for (int j = 0; j < 8; j++) {
            int2 mk0 = *(const int2*)(mrow0 + kt * 64 + j * 8 + c2);
            int2 mk1 = *(const int2*)(mrow1 + kt * 64 + j * 8 + c2);
            c[j][0] = mk0.x ? c[j][0] * scale : -1e9f;
            c[j][1] = mk0.y ? c[j][1] * scale : -1e9f;
            c[j][2] = mk1.x ? c[j][2] * scale : -1e9f;
            c[j][3] = mk1.y ? c[j][3] * scale : -1e9f;
        }

        // ---- online softmax ----
        float mx0 = c[0][0], mx1 = c[0][2];
#pragma unroll
        for (int j = 0; j < 8; j++) {
            mx0 = fmaxf(mx0, fmaxf(c[j][0], c[j][1]));
            mx1 = fmaxf(mx1, fmaxf(c[j][2], c[j][3]));
        }
        mx0 = fmaxf(mx0, __shfl_xor_sync(0xffffffffu, mx0, 1));
        mx0 = fmaxf(mx0, __shfl_xor_sync(0xffffffffu, mx0, 2));
        mx1 = fmaxf(mx1, __shfl_xor_sync(0xffffffffu, mx1, 1));
        mx1 = fmaxf(mx1, __shfl_xor_sync(0xffffffffu, mx1, 2));
        const float mn0 = fmaxf(m0, mx0), mn1 = fmaxf(m1, mx1);
        const float al0 = __expf(m0 - mn0), al1 = __expf(m1 - mn1);
        m0 = mn0; m1 = mn1;
        l0 *= al0; l1 *= al1;
#pragma unroll
        for (int j = 0; j < 8; j++) {
            o[j][0] *= al0; o[j][1] *= al0;
            o[j][2] *= al1; o[j][3] *= al1;
        }
#pragma unroll
        for (int j = 0; j < 8; j++) {
            c[j][0] = __expf(c[j][0] - mn0);
            c[j][1] = __expf(c[j][1] - mn0);
            c[j][2] = __expf(c[j][2] - mn1);
            c[j][3] = __expf(c[j][3] - mn1);
            l0 += c[j][0] + c[j][1];
            l1 += c[j][2] + c[j][3];
        }

        // ---- O += (Phi+Plo) * (Vhi+Vlo), 3 terms ----
#pragma unroll
        for (int jk = 0; jk < 4; jk++) {
            uint32_t ph[4], pl[4];
            {
                float* t0 = c[2*jk];
                float* t1 = c[2*jk + 1];
                uint16_t h00 = bf_hi(t0[0]), h01 = bf_hi(t0[1]);
                uint16_t h02 = bf_hi(t0[2]), h03 = bf_hi(t0[3]);
                uint16_t h10 = bf_hi(t1[0]), h11 = bf_hi(t1[1]);
                uint16_t h12 = bf_hi(t1[2]), h13 = bf_hi(t1[3]);
                ph[0] = pk(h00, h01); ph[1] = pk(h02, h03);
                ph[2] = pk(h10, h11); ph[3] = pk(h12, h13);
                pl[0] = pk(bf_hi(bf_res(t0[0], h00)), bf_hi(bf_res(t0[1], h01)));
                pl[1] = pk(bf_hi(bf_res(t0[2], h02)), bf_hi(bf_res(t0[3], h03)));
                pl[2] = pk(bf_hi(bf_res(t1[0], h10)), bf_hi(bf_res(t1[1], h11)));
                pl[3] = pk(bf_hi(bf_res(t1[2], h12)), bf_hi(bf_res(t1[3], h13)));
            }
#pragma unroll
            for (int jd2 = 0; jd2 < 4; jd2++) {
                uint32_t vh_[4], vl_[4];
                uint32_t vd = ss + 16384 + SW128((jk * 16 + aRow) * 128 + jd2 * 32 + aCol * 16);
                LDMX4T(vh_, vd);
                LDMX4T(vl_, vd + 8192);
                MMA16816(o[2*jd2],   ph, vh_[0], vh_[1]);
                MMA16816(o[2*jd2],   ph, vl_[0], vl_[1]);
                MMA16816(o[2*jd2],   pl, vh_[0], vh_[1]);
                MMA16816(o[2*jd2+1], ph, vh_[2], vh_[3]);
                MMA16816(o[2*jd2+1], ph, vl_[2], vl_[3]);
                MMA16816(o[2*jd2+1], pl, vh_[2], vh_[3]);
            }
        }
        __syncthreads();
    }

    // ---- epilogue: O/l -> bf16 hi/lo in ctx layout ----
    l0 += __shfl_xor_sync(0xffffffffu, l0, 1);
    l0 += __shfl_xor_sync(0xffffffffu, l0, 2);
    l1 += __shfl_xor_sync(0xffffffffu, l1, 1);
    l1 += __shfl_xor_sync(0xffffffffu, l1, 2);
    const float inv0 = 1.f / l0, inv1 = 1.f / l1;

    const size_t mbase0 = ((size_t)b * SEQ_ + row0) * DM_ + h * DK_;
    const size_t mbase1 = mbase0 + (size_t)8 * DM_;
#pragma unroll
    for (int jd = 0; jd < 8; jd++) {
        const int d = jd * 8 + c2;
        float v0 = o[jd][0] * inv0, v1 = o[jd][1] * inv0;
        float v2 = o[jd][2] * inv1, v3 = o[jd][3] * inv1;
        uint16_t h0 = bf_hi(v0), h1 = bf_hi(v1), h2 = bf_hi(v2), h3 = bf_hi(v3);
        *(uint32_t*)(Ohi + mbase0 + d) = pk(h0, h1);
        *(uint32_t*)(Olo + mbase0 + d) = pk(bf_hi(bf_res(v0, h0)), bf_hi(bf_res(v1, h1)));
        *(uint32_t*)(Ohi + mbase1 + d) = pk(h2, h3);
        *(uint32_t*)(Olo + mbase1 + d) = pk(bf_hi(bf_res(v2, h2)), bf_hi(bf_res(v3, h3)));
    }
}

// ---------------------------------------------------------------------------
extern "C" void kernel_launch(void* const* d_in, const int* in_sizes, int n_in,
                              void* d_out, int out_size)
{
    const float* q    = (const float*)d_in[0];
    const float* k    = (const float*)d_in[1];
    const float* v    = (const float*)d_in[2];
    const int*   mask = (const int*)  d_in[3];
    const float* Wq   = (const float*)d_in[4];
    const float* bq   = (const float*)d_in[5];
    const float* Wk   = (const float*)d_in[6];
    const float* bk   = (const float*)d_in[7];
    const float* Wv   = (const float*)d_in[8];
    const float* bv   = (const float*)d_in[9];
    const float* Wo   = (const float*)d_in[10];
    const float* bo   = (const float*)d_in[11];
    float* out = (float*)d_out;

    __nv_bfloat16 *pqh, *pql, *pkh, *pkl, *pvh, *pvl, *pAhi, *pAlo, *pWhi, *pWlo;
    cudaGetSymbolAddress((void**)&pqh,  g_qhi);
    cudaGetSymbolAddress((void**)&pql,  g_qlo);
    cudaGetSymbolAddress((void**)&pkh,  g_khi);
    cudaGetSymbolAddress((void**)&pkl,  g_klo);
    cudaGetSymbolAddress((void**)&pvh,  g_vhi);
    cudaGetSymbolAddress((void**)&pvl,  g_vlo);
    cudaGetSymbolAddress((void**)&pAhi, g_ahi);
    cudaGetSymbolAddress((void**)&pAlo, g_alo);
    cudaGetSymbolAddress((void**)&pWhi, g_whi);
    cudaGetSymbolAddress((void**)&pWlo, g_wlo);

    cudaFuncSetAttribute(gemm_mma_kernel, cudaFuncAttributeMaxDynamicSharedMemorySize, GEMM_SMEM);
    cudaFuncSetAttribute(attention_mma_kernel, cudaFuncAttributeMaxDynamicSharedMemorySize, AT_SMEM);

    const int nElem = M_ * DM_;
    dim3 splitGrid(nElem / 4 / 256);
    dim3 wGrid(32, 32), wBlock(32, 8);
    dim3 gemmGrid(DM_ / 128, M_ / 128);

    wsplit_kernel<<<wGrid, wBlock>>>(Wq, pWhi, pWlo);
    split_kernel<<<splitGrid, 256>>>(q, pAhi, pAlo, nElem);
    gemm_mma_kernel<<<gemmGrid, 256, GEMM_SMEM>>>(pAhi, pAlo, pWhi, pWlo, bq, nullptr, pqh, pql, 1);

    wsplit_kernel<<<wGrid, wBlock>>>(Wk, pWhi, pWlo);
    split_kernel<<<splitGrid, 256>>>(k, pAhi, pAlo, nElem);
    gemm_mma_kernel<<<gemmGrid, 256, GEMM_SMEM>>>(pAhi, pAlo, pWhi, pWlo, bk, nullptr, pkh, pkl, 1);

    wsplit_kernel<<<wGrid, wBlock>>>(Wv, pWhi, pWlo);
    split_kernel<<<splitGrid, 256>>>(v, pAhi, pAlo, nElem);
    gemm_mma_kernel<<<gemmGrid, 256, GEMM_SMEM>>>(pAhi, pAlo, pWhi, pWlo, bv, nullptr, pvh, pvl, 1);

    dim3 attnGrid(BH_, SEQ_ / 128);
    attention_mma_kernel<<<attnGrid, 256, AT_SMEM>>>(pqh, pql, pkh, pkl, pvh, pvl, mask, pAhi, pAlo);

    wsplit_kernel<<<wGrid, wBlock>>>(Wo, pWhi, pWlo);
    gemm_mma_kernel<<<gemmGrid, 256, GEMM_SMEM>>>(pAhi, pAlo, pWhi, pWlo, bo, out, nullptr, nullptr, 0);
}